// round 1
// baseline (speedup 1.0000x reference)
#include <cuda_runtime.h>
#include <cstdint>

// Problem constants
#define BATCH 16
#define CCH   512
#define HW    4096
#define NGRP  32
#define CPG   16          // channels per group
#define NH    8
#define HD    64
#define EPSV  1e-5f

// ---------------------------------------------------------------------------
// Scratch (device globals — no cudaMalloc allowed)
// ---------------------------------------------------------------------------
__device__ float g_qkv[(size_t)BATCH * 3 * CCH * HW];   // 384 MB
__device__ float g_attnout[(size_t)BATCH * CCH * HW];   // 128 MB
__device__ float g_sc[BATCH * CCH];                     // fused GN scale per (b,c)
__device__ float g_bs[BATCH * CCH];                     // fused GN bias  per (b,c)

// ---------------------------------------------------------------------------
// Kernel 1: GroupNorm statistics -> fused per-channel scale/bias
//   xn[b,c,n] = x[b,c,n] * g_sc[b,c] + g_bs[b,c]
// ---------------------------------------------------------------------------
__global__ __launch_bounds__(256) void gn_stats_kernel(
    const float* __restrict__ x,
    const float* __restrict__ gamma,
    const float* __restrict__ beta)
{
    int bg = blockIdx.x;           // b*NGRP + g
    int b = bg / NGRP, g = bg % NGRP;
    const float* xp = x + ((size_t)b * CCH + (size_t)g * CPG) * HW;  // contiguous 65536 floats

    int tid = threadIdx.x;
    float s = 0.f, ss = 0.f;
    const float4* xp4 = (const float4*)xp;
    const int n4 = (CPG * HW) / 4;  // 16384
    for (int i = tid; i < n4; i += 256) {
        float4 v = xp4[i];
        s  += v.x + v.y + v.z + v.w;
        ss += v.x*v.x + v.y*v.y + v.z*v.z + v.w*v.w;
    }
    __shared__ float sh_s[256], sh_ss[256];
    sh_s[tid] = s; sh_ss[tid] = ss;
    __syncthreads();
    for (int off = 128; off > 0; off >>= 1) {
        if (tid < off) { sh_s[tid] += sh_s[tid+off]; sh_ss[tid] += sh_ss[tid+off]; }
        __syncthreads();
    }
    if (tid < CPG) {
        const float inv_n = 1.0f / (float)(CPG * HW);
        float mean = sh_s[0] * inv_n;
        float var  = sh_ss[0] * inv_n - mean * mean;
        float inv  = rsqrtf(var + EPSV);
        int c = g * CPG + tid;
        float ga = gamma[c], be = beta[c];
        g_sc[b * CCH + c] = ga * inv;
        g_bs[b * CCH + c] = be - mean * inv * ga;
    }
}

// ---------------------------------------------------------------------------
// Kernel 2: tiled SGEMM  C[b] = A[M,K] * B[b][K,HW] (+bias[m]) (+res[b][m,n])
//   AFFINE: apply per-row (channel) scale/bias to B elements while loading
//           (this fuses GroupNorm normalization into the qkv GEMM)
// BM=BN=128, BK=16, 256 threads, 8x8 per-thread microtile.
// All dims divisible by tiles -> no bounds checks.
// ---------------------------------------------------------------------------
template<bool AFFINE, bool RES>
__global__ __launch_bounds__(256) void gemm128_kernel(
    const float* __restrict__ A,     // [M,K] row-major
    const float* __restrict__ Bm,    // base of batched B, stride K*HW per batch
    float* __restrict__ Cm,          // base of batched C, stride M*HW per batch
    const float* __restrict__ bias,  // [M]
    const float* __restrict__ res,   // batched residual, stride M*HW (only if RES)
    int M, int K)
{
    const int BM = 128, BN = 128, BK = 16;
    int b  = blockIdx.z;
    int n0 = blockIdx.x * BN;
    int m0 = blockIdx.y * BM;
    const float* Bp = Bm + (size_t)b * K * HW;
    float*       Cp = Cm + (size_t)b * M * HW;

    __shared__ float As[BK][BM];
    __shared__ float Bs[BK][BN];

    int tid  = threadIdx.x;          // 0..255
    int rowT = tid >> 4;             // 0..15
    int colT = tid & 15;             // 0..15

    float acc[8][8];
    #pragma unroll
    for (int i = 0; i < 8; i++)
        #pragma unroll
        for (int j = 0; j < 8; j++) acc[i][j] = 0.f;

    const float* scp = AFFINE ? (g_sc + b * CCH) : nullptr;
    const float* bsp = AFFINE ? (g_bs + b * CCH) : nullptr;

    for (int k0 = 0; k0 < K; k0 += BK) {
        // Load A tile (128 rows x 16 cols) as float4 along K, store transposed
        {
            int idx = tid;                      // 512 float4 total, 2 per thread
            #pragma unroll
            for (int r = 0; r < 2; r++, idx += 256) {
                int arow  = idx >> 2;           // 0..127
                int acol4 = idx & 3;            // 0..3
                float4 v = *(const float4*)(A + (size_t)(m0 + arow) * K + k0 + acol4 * 4);
                As[acol4*4+0][arow] = v.x;
                As[acol4*4+1][arow] = v.y;
                As[acol4*4+2][arow] = v.z;
                As[acol4*4+3][arow] = v.w;
            }
        }
        // Load B tile (16 rows x 128 cols), optionally apply GN affine per row
        {
            int idx = tid;                      // 512 float4 total, 2 per thread
            #pragma unroll
            for (int r = 0; r < 2; r++, idx += 256) {
                int brow  = idx >> 5;           // 0..15 (32 float4 per row)
                int bcol4 = idx & 31;
                float4 v = *(const float4*)(Bp + (size_t)(k0 + brow) * HW + n0 + bcol4 * 4);
                if (AFFINE) {
                    float sc = scp[k0 + brow], bs = bsp[k0 + brow];
                    v.x = fmaf(v.x, sc, bs); v.y = fmaf(v.y, sc, bs);
                    v.z = fmaf(v.z, sc, bs); v.w = fmaf(v.w, sc, bs);
                }
                *(float4*)(&Bs[brow][bcol4 * 4]) = v;
            }
        }
        __syncthreads();

        #pragma unroll
        for (int kk = 0; kk < BK; kk++) {
            float ra[8], rb[8];
            #pragma unroll
            for (int i = 0; i < 8; i++) ra[i] = As[kk][rowT * 8 + i];
            #pragma unroll
            for (int j = 0; j < 8; j++) rb[j] = Bs[kk][colT * 8 + j];
            #pragma unroll
            for (int i = 0; i < 8; i++)
                #pragma unroll
                for (int j = 0; j < 8; j++)
                    acc[i][j] = fmaf(ra[i], rb[j], acc[i][j]);
        }
        __syncthreads();
    }

    // Epilogue: +bias (+residual), vectorized stores
    #pragma unroll
    for (int i = 0; i < 8; i++) {
        int m = m0 + rowT * 8 + i;
        float bv = bias[m];
        #pragma unroll
        for (int j = 0; j < 8; j += 4) {
            int n = n0 + colT * 8 + j;
            float4 o;
            o.x = acc[i][j+0] + bv; o.y = acc[i][j+1] + bv;
            o.z = acc[i][j+2] + bv; o.w = acc[i][j+3] + bv;
            if (RES) {
                float4 rv = *(const float4*)(res + (size_t)b * M * HW + (size_t)m * HW + n);
                o.x += rv.x; o.y += rv.y; o.z += rv.z; o.w += rv.w;
            }
            *(float4*)(Cp + (size_t)m * HW + n) = o;
        }
    }
}

// ---------------------------------------------------------------------------
// Kernel 3: attention per (b,h).
//   S[64,64] = q[64,4096] * k[64,4096]^T * scale  (contraction over spatial)
//   P = softmax_rows(S)
//   O[64,4096] = P * v[64,4096]
// One block per (b,h) = 128 blocks, 256 threads.
// ---------------------------------------------------------------------------
__global__ __launch_bounds__(256) void attn_kernel()
{
    int b = blockIdx.x / NH, h = blockIdx.x % NH;
    const float* q = g_qkv + ((size_t)b * 3 * CCH + (size_t)h * HD) * HW;
    const float* k = g_qkv + ((size_t)b * 3 * CCH + CCH + (size_t)h * HD) * HW;
    const float* v = g_qkv + ((size_t)b * 3 * CCH + 2 * CCH + (size_t)h * HD) * HW;
    float*       o = g_attnout + ((size_t)b * CCH + (size_t)h * HD) * HW;

    __shared__ float qs[HD][33];
    __shared__ float ks[HD][33];
    __shared__ float P[HD][HD + 1];

    int tid = threadIdx.x;
    int ty = tid >> 4, tx = tid & 15;   // 16x16 thread grid, 4x4 outputs each

    float acc[4][4] = {};
    for (int n0 = 0; n0 < HW; n0 += 32) {
        for (int i = tid; i < HD * 32; i += 256) {
            int r = i >> 5, cc = i & 31;
            qs[r][cc] = q[(size_t)r * HW + n0 + cc];
            ks[r][cc] = k[(size_t)r * HW + n0 + cc];
        }
        __syncthreads();
        #pragma unroll
        for (int kk = 0; kk < 32; kk++) {
            float rq[4], rk[4];
            #pragma unroll
            for (int i = 0; i < 4; i++) rq[i] = qs[ty * 4 + i][kk];
            #pragma unroll
            for (int j = 0; j < 4; j++) rk[j] = ks[tx * 4 + j][kk];
            #pragma unroll
            for (int i = 0; i < 4; i++)
                #pragma unroll
                for (int j = 0; j < 4; j++)
                    acc[i][j] = fmaf(rq[i], rk[j], acc[i][j]);
        }
        __syncthreads();
    }

    const float scale = 0.125f;   // 1/sqrt(64)
    #pragma unroll
    for (int i = 0; i < 4; i++)
        #pragma unroll
        for (int j = 0; j < 4; j++)
            P[ty * 4 + i][tx * 4 + j] = acc[i][j] * scale;
    __syncthreads();

    // row softmax (one thread per row; padded stride keeps banks clean)
    if (tid < HD) {
        float mx = -1e30f;
        #pragma unroll 8
        for (int j = 0; j < HD; j++) mx = fmaxf(mx, P[tid][j]);
        float sum = 0.f;
        #pragma unroll 8
        for (int j = 0; j < HD; j++) { float e = __expf(P[tid][j] - mx); P[tid][j] = e; sum += e; }
        float inv = 1.f / sum;
        #pragma unroll 8
        for (int j = 0; j < HD; j++) P[tid][j] *= inv;
    }
    __syncthreads();

    // O = P @ v : each thread owns 16 spatial columns
    for (int n = tid; n < HW; n += 256) {
        float accv[HD];
        #pragma unroll
        for (int cc = 0; cc < HD; cc++) accv[cc] = 0.f;
        #pragma unroll 4
        for (int d = 0; d < HD; d++) {
            float vd = v[(size_t)d * HW + n];
            #pragma unroll
            for (int cc = 0; cc < HD; cc++)
                accv[cc] = fmaf(P[cc][d], vd, accv[cc]);
        }
        #pragma unroll
        for (int cc = 0; cc < HD; cc++)
            o[(size_t)cc * HW + n] = accv[cc];
    }
}

// ---------------------------------------------------------------------------
// Launch
// ---------------------------------------------------------------------------
extern "C" void kernel_launch(void* const* d_in, const int* in_sizes, int n_in,
                              void* d_out, int out_size)
{
    const float* x      = (const float*)d_in[0];
    const float* gamma  = (const float*)d_in[1];
    const float* beta   = (const float*)d_in[2];
    const float* w_qkv  = (const float*)d_in[3];
    const float* b_qkv  = (const float*)d_in[4];
    const float* w_proj = (const float*)d_in[5];
    const float* b_proj = (const float*)d_in[6];
    float* out = (float*)d_out;

    float *qkv_ptr, *ao_ptr;
    cudaGetSymbolAddress((void**)&qkv_ptr, g_qkv);
    cudaGetSymbolAddress((void**)&ao_ptr, g_attnout);

    // 1) GroupNorm stats -> fused scale/bias
    gn_stats_kernel<<<BATCH * NGRP, 256>>>(x, gamma, beta);

    // 2) qkv = w_qkv @ GN(x) + b_qkv   (GN folded into B-tile load)
    {
        dim3 grid(HW / 128, (3 * CCH) / 128, BATCH);
        gemm128_kernel<true, false><<<grid, 256>>>(
            w_qkv, x, qkv_ptr, b_qkv, nullptr, 3 * CCH, CCH);
    }

    // 3) attention per (b,h)
    attn_kernel<<<BATCH * NH, 256>>>();

    // 4) out = w_proj @ attnout + b_proj + x
    {
        dim3 grid(HW / 128, CCH / 128, BATCH);
        gemm128_kernel<false, true><<<grid, 256>>>(
            w_proj, ao_ptr, out, b_proj, x, CCH, CCH);
    }
}

// round 3
// speedup vs baseline: 2.0484x; 2.0484x over previous
#include <cuda_runtime.h>
#include <cstdint>

// Problem constants
#define BATCH 16
#define CCH   512
#define HW    4096
#define NGRP  32
#define CPG   16
#define NH    8
#define HD    64
#define EPSV  1e-5f

// ---------------------------------------------------------------------------
// Scratch (device globals)
// ---------------------------------------------------------------------------
__device__ float g_qkv[(size_t)BATCH * 3 * CCH * HW];   // [b][o][n]
__device__ float g_ao [(size_t)BATCH * CCH * HW];       // [b][c][n]
__device__ float g_sc[BATCH * CCH];
__device__ float g_bs[BATCH * CCH];

// ---------------------------------------------------------------------------
// Kernel 1: GroupNorm stats -> fused per-channel scale/bias
// ---------------------------------------------------------------------------
__global__ __launch_bounds__(256) void gn_stats_kernel(
    const float* __restrict__ x,
    const float* __restrict__ gamma,
    const float* __restrict__ beta)
{
    int bg = blockIdx.x;
    int b = bg / NGRP, g = bg % NGRP;
    const float* xp = x + ((size_t)b * CCH + (size_t)g * CPG) * HW;

    int tid = threadIdx.x;
    float s = 0.f, ss = 0.f;
    const float4* xp4 = (const float4*)xp;
    const int n4 = (CPG * HW) / 4;
    for (int i = tid; i < n4; i += 256) {
        float4 v = xp4[i];
        s  += v.x + v.y + v.z + v.w;
        ss += v.x*v.x + v.y*v.y + v.z*v.z + v.w*v.w;
    }
    __shared__ float sh_s[256], sh_ss[256];
    sh_s[tid] = s; sh_ss[tid] = ss;
    __syncthreads();
    for (int off = 128; off > 0; off >>= 1) {
        if (tid < off) { sh_s[tid] += sh_s[tid+off]; sh_ss[tid] += sh_ss[tid+off]; }
        __syncthreads();
    }
    if (tid < CPG) {
        const float inv_n = 1.0f / (float)(CPG * HW);
        float mean = sh_s[0] * inv_n;
        float var  = sh_ss[0] * inv_n - mean * mean;
        float inv  = rsqrtf(var + EPSV);
        int c = g * CPG + tid;
        float ga = gamma[c], be = beta[c];
        g_sc[b * CCH + c] = ga * inv;
        g_bs[b * CCH + c] = be - mean * inv * ga;
    }
}

// ---------------------------------------------------------------------------
// Kernel 2: TF32 mma.sync GEMM.
//   C[b][o][n] = sum_c W[o][c] * X[b][c][n]   (+bias[o]) (+res)
//   MODE 0: X = x with GN affine fused (scale/bias from g_sc/g_bs)
//   MODE 1: X = g_ao, residual added, writes d_out
// CTA 128x128, BK=16, 8 warps @ 64x32 warp tiles, m16n8k8 tf32 fragments.
// ---------------------------------------------------------------------------
#define BK   16
#define SSTR 136   // smem row stride in words (8k + col covers all banks)

__device__ __forceinline__ uint32_t f2t(float f) {
    uint32_t u;
    asm("cvt.rna.tf32.f32 %0, %1;" : "=r"(u) : "f"(f));
    return u;
}

template<int MODE>
__global__ __launch_bounds__(256, 2) void gemm_mma(
    const float* __restrict__ Xsrc,   // MODE0: x ; MODE1: g_ao   [b][c][n]
    const float* __restrict__ W,      // [MO, 512] row-major
    const float* __restrict__ bias,   // [MO]
    const float* __restrict__ res,    // MODE1: x (residual) [b][o][n]
    float* __restrict__ Out,          // [b][MO][n]
    int MO)
{
    __shared__ uint32_t Ws[2][BK][SSTR];   // [k][m] with XOR swizzle on m
    __shared__ uint32_t Xs[2][BK][SSTR];   // [k][n]
    __shared__ float scs[CCH], bss[CCH];

    const int tid  = threadIdx.x;
    const int lane = tid & 31;
    const int wid  = tid >> 5;
    const int b  = blockIdx.z;
    const int n0 = blockIdx.x * 128;
    const int o0 = blockIdx.y * 128;

    const float* Xp = Xsrc + (size_t)b * CCH * HW;

    if (MODE == 0) {
        for (int i = tid; i < CCH; i += 256) {
            scs[i] = g_sc[b * CCH + i];
            bss[i] = g_bs[b * CCH + i];
        }
    }
    __syncthreads();

    // global-load thread mapping
    const int xk  = tid >> 5;   // 0..7   (+8 for second row)
    const int xn4 = tid & 31;   // float4 index along n
    const int wmr = tid >> 2;   // 0..63  (+64 for second row)
    const int wkq = tid & 3;    // float4 index along k

    // warp tile coords
    const int wm = wid >> 2, wn = wid & 3;
    const int mb = wm * 64, nb = wn * 32;
    const int g4 = lane >> 2, t4 = lane & 3;

    float acc[4][4][4];
    #pragma unroll
    for (int i = 0; i < 4; i++)
        #pragma unroll
        for (int j = 0; j < 4; j++)
            #pragma unroll
            for (int r = 0; r < 4; r++) acc[i][j][r] = 0.f;

    float4 rx[2], rw[2];
    auto ldg = [&](int s) {
        const int k0 = s * BK;
        #pragma unroll
        for (int i = 0; i < 2; i++) {
            int k = xk + i * 8;
            rx[i] = *(const float4*)(Xp + (size_t)(k0 + k) * HW + n0 + xn4 * 4);
            if (MODE == 0) {
                float sc = scs[k0 + k], bs = bss[k0 + k];
                rx[i].x = fmaf(rx[i].x, sc, bs); rx[i].y = fmaf(rx[i].y, sc, bs);
                rx[i].z = fmaf(rx[i].z, sc, bs); rx[i].w = fmaf(rx[i].w, sc, bs);
            }
            rw[i] = *(const float4*)(W + (size_t)(o0 + wmr + i * 64) * CCH + k0 + wkq * 4);
        }
    };
    auto sts = [&](int buf) {
        #pragma unroll
        for (int i = 0; i < 2; i++) {
            uint32_t* px = &Xs[buf][xk + i * 8][xn4 * 4];
            *(uint4*)px = make_uint4(f2t(rx[i].x), f2t(rx[i].y), f2t(rx[i].z), f2t(rx[i].w));
            int m = wmr + i * 64;
            #pragma unroll
            for (int j = 0; j < 4; j++) {
                int k = wkq * 4 + j;
                int ms = m ^ (((k >> 2) & 3) << 3);    // bank swizzle
                float v = j == 0 ? rw[i].x : j == 1 ? rw[i].y : j == 2 ? rw[i].z : rw[i].w;
                Ws[buf][k][ms] = f2t(v);
            }
        }
    };

    ldg(0);
    sts(0);
    __syncthreads();

    const int NS = CCH / BK;   // 32
    #pragma unroll 1
    for (int s = 0; s < NS; s++) {
        const int buf = s & 1;
        if (s + 1 < NS) ldg(s + 1);

        #pragma unroll
        for (int ks = 0; ks < 2; ks++) {
            const int kk = ks * 8;
            uint32_t a[4][4], bb[4][2];
            const int swz0 = (((kk + t4)     >> 2) & 3) << 3;
            const int swz1 = (((kk + 4 + t4) >> 2) & 3) << 3;
            #pragma unroll
            for (int mf = 0; mf < 4; mf++) {
                int row = mb + mf * 16 + g4;
                a[mf][0] = Ws[buf][kk + t4    ][row ^ swz0];
                a[mf][1] = Ws[buf][kk + t4    ][(row + 8) ^ swz0];
                a[mf][2] = Ws[buf][kk + 4 + t4][row ^ swz1];
                a[mf][3] = Ws[buf][kk + 4 + t4][(row + 8) ^ swz1];
            }
            #pragma unroll
            for (int nf = 0; nf < 4; nf++) {
                int col = nb + nf * 8 + g4;
                bb[nf][0] = Xs[buf][kk + t4    ][col];
                bb[nf][1] = Xs[buf][kk + 4 + t4][col];
            }
            #pragma unroll
            for (int mf = 0; mf < 4; mf++)
                #pragma unroll
                for (int nf = 0; nf < 4; nf++)
                    asm volatile(
                        "mma.sync.aligned.m16n8k8.row.col.f32.tf32.tf32.f32 "
                        "{%0,%1,%2,%3}, {%4,%5,%6,%7}, {%8,%9}, {%0,%1,%2,%3};"
                        : "+f"(acc[mf][nf][0]), "+f"(acc[mf][nf][1]),
                          "+f"(acc[mf][nf][2]), "+f"(acc[mf][nf][3])
                        : "r"(a[mf][0]), "r"(a[mf][1]), "r"(a[mf][2]), "r"(a[mf][3]),
                          "r"(bb[nf][0]), "r"(bb[nf][1]));
        }

        if (s + 1 < NS) sts(buf ^ 1);
        __syncthreads();
    }

    // ---- epilogue: +bias (+residual), float2 stores ----
    #pragma unroll
    for (int mf = 0; mf < 4; mf++) {
        int row = o0 + mb + mf * 16 + g4;
        float bv0 = bias[row], bv1 = bias[row + 8];
        #pragma unroll
        for (int nf = 0; nf < 4; nf++) {
            int col = n0 + nb + nf * 8 + t4 * 2;
            size_t a0 = ((size_t)b * MO + row)     * HW + col;
            size_t a1 = ((size_t)b * MO + row + 8) * HW + col;
            float2 v0 = { acc[mf][nf][0] + bv0, acc[mf][nf][1] + bv0 };
            float2 v1 = { acc[mf][nf][2] + bv1, acc[mf][nf][3] + bv1 };
            if (MODE == 1) {
                float2 r0 = *(const float2*)(res + a0);
                float2 r1 = *(const float2*)(res + a1);
                v0.x += r0.x; v0.y += r0.y;
                v1.x += r1.x; v1.y += r1.y;
            }
            *(float2*)(Out + a0) = v0;
            *(float2*)(Out + a1) = v1;
        }
    }
}

// ---------------------------------------------------------------------------
// Kernel 3: attention per (b,h)   (layout [b][o][n], proven in round 1)
// ---------------------------------------------------------------------------
__global__ __launch_bounds__(256) void attn_kernel()
{
    int b = blockIdx.x / NH, h = blockIdx.x % NH;
    const float* q = g_qkv + ((size_t)b * 3 * CCH + (size_t)h * HD) * HW;
    const float* k = g_qkv + ((size_t)b * 3 * CCH + CCH + (size_t)h * HD) * HW;
    const float* v = g_qkv + ((size_t)b * 3 * CCH + 2 * CCH + (size_t)h * HD) * HW;
    float*       o = g_ao  + ((size_t)b * CCH + (size_t)h * HD) * HW;

    __shared__ float qs[HD][33];
    __shared__ float ks[HD][33];
    __shared__ float P[HD][HD + 1];

    int tid = threadIdx.x;
    int ty = tid >> 4, tx = tid & 15;

    float acc[4][4] = {};
    for (int n0 = 0; n0 < HW; n0 += 32) {
        for (int i = tid; i < HD * 32; i += 256) {
            int r = i >> 5, cc = i & 31;
            qs[r][cc] = q[(size_t)r * HW + n0 + cc];
            ks[r][cc] = k[(size_t)r * HW + n0 + cc];
        }
        __syncthreads();
        #pragma unroll
        for (int kk = 0; kk < 32; kk++) {
            float rq[4], rk[4];
            #pragma unroll
            for (int i = 0; i < 4; i++) rq[i] = qs[ty * 4 + i][kk];
            #pragma unroll
            for (int j = 0; j < 4; j++) rk[j] = ks[tx * 4 + j][kk];
            #pragma unroll
            for (int i = 0; i < 4; i++)
                #pragma unroll
                for (int j = 0; j < 4; j++)
                    acc[i][j] = fmaf(rq[i], rk[j], acc[i][j]);
        }
        __syncthreads();
    }

    const float scale = 0.125f;
    #pragma unroll
    for (int i = 0; i < 4; i++)
        #pragma unroll
        for (int j = 0; j < 4; j++)
            P[ty * 4 + i][tx * 4 + j] = acc[i][j] * scale;
    __syncthreads();

    if (tid < HD) {
        float mx = -1e30f;
        #pragma unroll 8
        for (int j = 0; j < HD; j++) mx = fmaxf(mx, P[tid][j]);
        float sum = 0.f;
        #pragma unroll 8
        for (int j = 0; j < HD; j++) { float e = __expf(P[tid][j] - mx); P[tid][j] = e; sum += e; }
        float inv = 1.f / sum;
        #pragma unroll 8
        for (int j = 0; j < HD; j++) P[tid][j] *= inv;
    }
    __syncthreads();

    for (int n = tid; n < HW; n += 256) {
        float accv[HD];
        #pragma unroll
        for (int cc = 0; cc < HD; cc++) accv[cc] = 0.f;
        #pragma unroll 4
        for (int d = 0; d < HD; d++) {
            float vd = v[(size_t)d * HW + n];
            #pragma unroll
            for (int cc = 0; cc < HD; cc++)
                accv[cc] = fmaf(P[cc][d], vd, accv[cc]);
        }
        #pragma unroll
        for (int cc = 0; cc < HD; cc++)
            o[(size_t)cc * HW + n] = accv[cc];
    }
}

// ---------------------------------------------------------------------------
// Launch
// ---------------------------------------------------------------------------
extern "C" void kernel_launch(void* const* d_in, const int* in_sizes, int n_in,
                              void* d_out, int out_size)
{
    const float* x      = (const float*)d_in[0];
    const float* gamma  = (const float*)d_in[1];
    const float* beta   = (const float*)d_in[2];
    const float* w_qkv  = (const float*)d_in[3];
    const float* b_qkv  = (const float*)d_in[4];
    const float* w_proj = (const float*)d_in[5];
    const float* b_proj = (const float*)d_in[6];
    float* out = (float*)d_out;

    float *qkv_ptr, *ao_ptr;
    cudaGetSymbolAddress((void**)&qkv_ptr, g_qkv);
    cudaGetSymbolAddress((void**)&ao_ptr, g_ao);

    // 1) GroupNorm stats
    gn_stats_kernel<<<BATCH * NGRP, 256>>>(x, gamma, beta);

    // 2) qkv GEMM (tf32 mma.sync), GN fused into X load
    {
        dim3 grid(HW / 128, (3 * CCH) / 128, BATCH);   // 32 x 12 x 16
        gemm_mma<0><<<grid, 256>>>(x, w_qkv, b_qkv, nullptr, qkv_ptr, 3 * CCH);
    }

    // 3) attention
    attn_kernel<<<BATCH * NH, 256>>>();

    // 4) proj GEMM (tf32 mma.sync), bias+residual fused
    {
        dim3 grid(HW / 128, CCH / 128, BATCH);         // 32 x 4 x 16
        gemm_mma<1><<<grid, 256>>>(ao_ptr, w_proj, b_proj, x, out, CCH);
    }
}

// round 4
// speedup vs baseline: 2.4134x; 1.1782x over previous
#include <cuda_runtime.h>
#include <cstdint>

// Problem constants
#define BATCH 16
#define CCH   512
#define HW    4096
#define NGRP  32
#define CPG   16
#define NH    8
#define HD    64
#define EPSV  1e-5f
#define ACH   8            // attention spatial chunks
#define CLEN  (HW / ACH)   // 512

// ---------------------------------------------------------------------------
// Scratch (device globals)
// ---------------------------------------------------------------------------
__device__ float g_qkv[(size_t)BATCH * 3 * CCH * HW];   // [b][o][n]
__device__ float g_ao [(size_t)BATCH * CCH * HW];       // [b][c][n]  (tf32-rounded)
__device__ float g_sc[BATCH * CCH];
__device__ float g_bs[BATCH * CCH];
__device__ uint32_t g_wtq[CCH * 3 * CCH];               // W_qkv^T [k][o], tf32 bits
__device__ uint32_t g_wtp[CCH * CCH];                   // W_proj^T [k][o], tf32 bits
__device__ float g_sp[(size_t)BATCH * NH * ACH * HD * HD];  // S partials
__device__ float g_P [(size_t)BATCH * NH * HD * HD];        // softmaxed P

// ---------------------------------------------------------------------------
// helpers
// ---------------------------------------------------------------------------
__device__ __forceinline__ uint32_t f2t(float f) {
    uint32_t u;
    asm("cvt.rna.tf32.f32 %0, %1;" : "=r"(u) : "f"(f));
    return u;
}
__device__ __forceinline__ uint32_t sptr(const void* p) {
    uint32_t a;
    asm("{ .reg .u64 t; cvta.to.shared.u64 t, %1; cvt.u32.u64 %0, t; }" : "=r"(a) : "l"(p));
    return a;
}
__device__ __forceinline__ void cpa16(uint32_t dst, const void* src) {
    asm volatile("cp.async.cg.shared.global [%0], [%1], 16;" :: "r"(dst), "l"(src));
}
__device__ __forceinline__ void cpa_commit() { asm volatile("cp.async.commit_group;" ::: "memory"); }
__device__ __forceinline__ void cpa_wait0()  { asm volatile("cp.async.wait_group 0;" ::: "memory"); }

// ---------------------------------------------------------------------------
// Kernel 0: transpose + tf32-convert weights  W[o][k] -> WT[k][o]
// ---------------------------------------------------------------------------
__global__ __launch_bounds__(256) void wt_kernel(
    const float* __restrict__ Wq, const float* __restrict__ Wp)
{
    int gt = blockIdx.x * 256 + threadIdx.x;
    int stride = gridDim.x * 256;
    for (int i = gt; i < CCH * 3 * CCH; i += stride) {
        int k = i / (3 * CCH), o = i % (3 * CCH);
        g_wtq[i] = f2t(Wq[(size_t)o * CCH + k]);
    }
    for (int i = gt; i < CCH * CCH; i += stride) {
        int k = i >> 9, o = i & 511;
        g_wtp[i] = f2t(Wp[(size_t)o * CCH + k]);
    }
}

// ---------------------------------------------------------------------------
// Kernel 1: GroupNorm stats -> fused per-channel scale/bias
// ---------------------------------------------------------------------------
__global__ __launch_bounds__(256) void gn_stats_kernel(
    const float* __restrict__ x,
    const float* __restrict__ gamma,
    const float* __restrict__ beta)
{
    int bg = blockIdx.x;
    int b = bg / NGRP, g = bg % NGRP;
    const float* xp = x + ((size_t)b * CCH + (size_t)g * CPG) * HW;

    int tid = threadIdx.x;
    float s = 0.f, ss = 0.f;
    const float4* xp4 = (const float4*)xp;
    const int n4 = (CPG * HW) / 4;
    for (int i = tid; i < n4; i += 256) {
        float4 v = xp4[i];
        s  += v.x + v.y + v.z + v.w;
        ss += v.x*v.x + v.y*v.y + v.z*v.z + v.w*v.w;
    }
    __shared__ float sh_s[256], sh_ss[256];
    sh_s[tid] = s; sh_ss[tid] = ss;
    __syncthreads();
    for (int off = 128; off > 0; off >>= 1) {
        if (tid < off) { sh_s[tid] += sh_s[tid+off]; sh_ss[tid] += sh_ss[tid+off]; }
        __syncthreads();
    }
    if (tid < CPG) {
        const float inv_n = 1.0f / (float)(CPG * HW);
        float mean = sh_s[0] * inv_n;
        float var  = sh_ss[0] * inv_n - mean * mean;
        float inv  = rsqrtf(var + EPSV);
        int c = g * CPG + tid;
        float ga = gamma[c], be = beta[c];
        g_sc[b * CCH + c] = ga * inv;
        g_bs[b * CCH + c] = be - mean * inv * ga;
    }
}

// ---------------------------------------------------------------------------
// Kernel 2: TF32 mma.sync GEMM (swizzle-free smem, cp.async W tiles)
//   C[b][o][n] = sum_k WT[k][o] * X[b][k][n]  (+bias[o]) (+res)
//   MODE 0: X = x with GN affine fused (register path + cvt.rna)
//   MODE 1: X = g_ao (already tf32-exact) via cp.async; +residual -> d_out
// ---------------------------------------------------------------------------
#define BK   16
#define SSTR 136

template<int MODE>
__global__ __launch_bounds__(256, 2) void gemm_mma(
    const float* __restrict__ Xsrc,
    const uint32_t* __restrict__ WT,   // [512][MO] tf32 bits
    const float* __restrict__ bias,
    const float* __restrict__ res,
    float* __restrict__ Out,
    int MO)
{
    __shared__ uint32_t Ws[2][BK][SSTR];
    __shared__ uint32_t Xs[2][BK][SSTR];
    __shared__ float scs[CCH], bss[CCH];

    const int tid  = threadIdx.x;
    const int lane = tid & 31;
    const int wid  = tid >> 5;
    const int b  = blockIdx.z;
    const int n0 = blockIdx.x * 128;
    const int o0 = blockIdx.y * 128;

    const float* Xp = Xsrc + (size_t)b * CCH * HW;

    if (MODE == 0) {
        for (int i = tid; i < CCH; i += 256) {
            scs[i] = g_sc[b * CCH + i];
            bss[i] = g_bs[b * CCH + i];
        }
        __syncthreads();
    }

    const uint32_t wsb = sptr(&Ws[0][0][0]);
    const uint32_t xsb = sptr(&Xs[0][0][0]);
    const uint32_t BUFB = BK * SSTR * 4;   // bytes per buffer

    // cp.async mapping: 512 x 16B per tile, 2 per thread
    const int cr0 = tid >> 5;           // idx = tid   : kr 0..7
    const int cm0 = tid & 31;
    // second chunk: idx = tid+256 -> kr = cr0+8, same cm

    // MODE0 X register-path mapping
    const int xk  = tid >> 5;
    const int xn4 = tid & 31;

    // warp tile coords
    const int wm = wid >> 2, wn = wid & 3;
    const int mb = wm * 64, nb = wn * 32;
    const int g4 = lane >> 2, t4 = lane & 3;

    float acc[4][4][4];
    #pragma unroll
    for (int i = 0; i < 4; i++)
        #pragma unroll
        for (int j = 0; j < 4; j++)
            #pragma unroll
            for (int r = 0; r < 4; r++) acc[i][j][r] = 0.f;

    auto issueW = [&](int s, int buf) {
        const int k0 = s * BK;
        #pragma unroll
        for (int i = 0; i < 2; i++) {
            int kr = cr0 + i * 8;
            cpa16(wsb + buf * BUFB + (uint32_t)(kr * SSTR + cm0 * 4) * 4,
                  WT + (size_t)(k0 + kr) * MO + o0 + cm0 * 4);
        }
    };
    auto issueX = [&](int s, int buf) {   // MODE 1 only
        const int k0 = s * BK;
        #pragma unroll
        for (int i = 0; i < 2; i++) {
            int kr = cr0 + i * 8;
            cpa16(xsb + buf * BUFB + (uint32_t)(kr * SSTR + cm0 * 4) * 4,
                  Xp + (size_t)(k0 + kr) * HW + n0 + cm0 * 4);
        }
    };
    float4 rx[2];
    auto ldgX = [&](int s) {              // MODE 0 only
        const int k0 = s * BK;
        #pragma unroll
        for (int i = 0; i < 2; i++) {
            int k = xk + i * 8;
            rx[i] = *(const float4*)(Xp + (size_t)(k0 + k) * HW + n0 + xn4 * 4);
            float sc = scs[k0 + k], bs = bss[k0 + k];
            rx[i].x = fmaf(rx[i].x, sc, bs); rx[i].y = fmaf(rx[i].y, sc, bs);
            rx[i].z = fmaf(rx[i].z, sc, bs); rx[i].w = fmaf(rx[i].w, sc, bs);
        }
    };
    auto stsX = [&](int buf) {
        #pragma unroll
        for (int i = 0; i < 2; i++) {
            uint32_t* px = &Xs[buf][xk + i * 8][xn4 * 4];
            *(uint4*)px = make_uint4(f2t(rx[i].x), f2t(rx[i].y), f2t(rx[i].z), f2t(rx[i].w));
        }
    };

    // prologue: stage 0
    issueW(0, 0);
    if (MODE == 1) issueX(0, 0);
    cpa_commit();
    if (MODE == 0) { ldgX(0); stsX(0); }
    cpa_wait0();
    __syncthreads();

    const int NS = CCH / BK;   // 32
    #pragma unroll 1
    for (int s = 0; s < NS; s++) {
        const int buf = s & 1;
        if (s + 1 < NS) {
            issueW(s + 1, buf ^ 1);
            if (MODE == 1) issueX(s + 1, buf ^ 1);
            cpa_commit();
            if (MODE == 0) ldgX(s + 1);
        }

        #pragma unroll
        for (int ks = 0; ks < 2; ks++) {
            const int kk = ks * 8;
            uint32_t a[4][4], bb[4][2];
            #pragma unroll
            for (int mf = 0; mf < 4; mf++) {
                int row = mb + mf * 16 + g4;
                a[mf][0] = Ws[buf][kk + t4    ][row];
                a[mf][1] = Ws[buf][kk + t4    ][row + 8];
                a[mf][2] = Ws[buf][kk + 4 + t4][row];
                a[mf][3] = Ws[buf][kk + 4 + t4][row + 8];
            }
            #pragma unroll
            for (int nf = 0; nf < 4; nf++) {
                int col = nb + nf * 8 + g4;
                bb[nf][0] = Xs[buf][kk + t4    ][col];
                bb[nf][1] = Xs[buf][kk + 4 + t4][col];
            }
            #pragma unroll
            for (int mf = 0; mf < 4; mf++)
                #pragma unroll
                for (int nf = 0; nf < 4; nf++)
                    asm volatile(
                        "mma.sync.aligned.m16n8k8.row.col.f32.tf32.tf32.f32 "
                        "{%0,%1,%2,%3}, {%4,%5,%6,%7}, {%8,%9}, {%0,%1,%2,%3};"
                        : "+f"(acc[mf][nf][0]), "+f"(acc[mf][nf][1]),
                          "+f"(acc[mf][nf][2]), "+f"(acc[mf][nf][3])
                        : "r"(a[mf][0]), "r"(a[mf][1]), "r"(a[mf][2]), "r"(a[mf][3]),
                          "r"(bb[nf][0]), "r"(bb[nf][1]));
        }

        if (s + 1 < NS) {
            if (MODE == 0) stsX(buf ^ 1);
            cpa_wait0();
        }
        __syncthreads();
    }

    // ---- epilogue ----
    #pragma unroll
    for (int mf = 0; mf < 4; mf++) {
        int row = o0 + mb + mf * 16 + g4;
        float bv0 = bias[row], bv1 = bias[row + 8];
        #pragma unroll
        for (int nf = 0; nf < 4; nf++) {
            int col = n0 + nb + nf * 8 + t4 * 2;
            size_t a0 = ((size_t)b * MO + row)     * HW + col;
            size_t a1 = ((size_t)b * MO + row + 8) * HW + col;
            float2 v0 = { acc[mf][nf][0] + bv0, acc[mf][nf][1] + bv0 };
            float2 v1 = { acc[mf][nf][2] + bv1, acc[mf][nf][3] + bv1 };
            if (MODE == 1) {
                float2 r0 = *(const float2*)(res + a0);
                float2 r1 = *(const float2*)(res + a1);
                v0.x += r0.x; v0.y += r0.y;
                v1.x += r1.x; v1.y += r1.y;
            }
            *(float2*)(Out + a0) = v0;
            *(float2*)(Out + a1) = v1;
        }
    }
}

// ---------------------------------------------------------------------------
// Kernel 3a: attention QK^T partials. grid = B*NH*ACH, 256 threads.
//   g_sp[bh*8+ch][c][d] = sum_{n in chunk} q[c][n] k[d][n]
// ---------------------------------------------------------------------------
__global__ __launch_bounds__(256) void attn_qk_kernel()
{
    int blk = blockIdx.x;
    int bh = blk >> 3, ch = blk & 7;
    int b = bh >> 3, h = bh & 7;
    const float* q = g_qkv + ((size_t)b * 3 * CCH + (size_t)h * HD) * HW;
    const float* k = g_qkv + ((size_t)b * 3 * CCH + CCH + (size_t)h * HD) * HW;

    __shared__ float qs[HD][33];
    __shared__ float ks[HD][33];

    int tid = threadIdx.x;
    int ty = tid >> 4, tx = tid & 15;

    float acc[4][4] = {};
    const int nbeg = ch * CLEN;
    for (int n0 = nbeg; n0 < nbeg + CLEN; n0 += 32) {
        for (int i = tid; i < HD * 32; i += 256) {
            int r = i >> 5, cc = i & 31;
            qs[r][cc] = q[(size_t)r * HW + n0 + cc];
            ks[r][cc] = k[(size_t)r * HW + n0 + cc];
        }
        __syncthreads();
        #pragma unroll
        for (int kk = 0; kk < 32; kk++) {
            float rq[4], rk[4];
            #pragma unroll
            for (int i = 0; i < 4; i++) rq[i] = qs[ty * 4 + i][kk];
            #pragma unroll
            for (int j = 0; j < 4; j++) rk[j] = ks[tx * 4 + j][kk];
            #pragma unroll
            for (int i = 0; i < 4; i++)
                #pragma unroll
                for (int j = 0; j < 4; j++)
                    acc[i][j] = fmaf(rq[i], rk[j], acc[i][j]);
        }
        __syncthreads();
    }

    float* sp = g_sp + (size_t)blk * (HD * HD);
    #pragma unroll
    for (int i = 0; i < 4; i++)
        #pragma unroll
        for (int j = 0; j < 4; j++)
            sp[(ty * 4 + i) * HD + tx * 4 + j] = acc[i][j];
}

// ---------------------------------------------------------------------------
// Kernel 3b: reduce partials + softmax. grid = B*NH, 64 threads (row each).
// ---------------------------------------------------------------------------
__global__ __launch_bounds__(64) void attn_sm_kernel()
{
    int bh = blockIdx.x;
    int r = threadIdx.x;

    float4 a[16];
    #pragma unroll
    for (int j = 0; j < 16; j++) a[j] = make_float4(0.f, 0.f, 0.f, 0.f);
    #pragma unroll
    for (int ch = 0; ch < ACH; ch++) {
        const float4* p = (const float4*)(g_sp + ((size_t)bh * ACH + ch) * (HD * HD) + r * HD);
        #pragma unroll
        for (int j = 0; j < 16; j++) {
            float4 v = p[j];
            a[j].x += v.x; a[j].y += v.y; a[j].z += v.z; a[j].w += v.w;
        }
    }
    const float scale = 0.125f;
    float mx = -1e30f;
    #pragma unroll
    for (int j = 0; j < 16; j++) {
        a[j].x *= scale; a[j].y *= scale; a[j].z *= scale; a[j].w *= scale;
        mx = fmaxf(mx, fmaxf(fmaxf(a[j].x, a[j].y), fmaxf(a[j].z, a[j].w)));
    }
    float sum = 0.f;
    #pragma unroll
    for (int j = 0; j < 16; j++) {
        a[j].x = __expf(a[j].x - mx); a[j].y = __expf(a[j].y - mx);
        a[j].z = __expf(a[j].z - mx); a[j].w = __expf(a[j].w - mx);
        sum += a[j].x + a[j].y + a[j].z + a[j].w;
    }
    float inv = 1.f / sum;
    float4* po = (float4*)(g_P + (size_t)bh * (HD * HD) + r * HD);
    #pragma unroll
    for (int j = 0; j < 16; j++) {
        a[j].x *= inv; a[j].y *= inv; a[j].z *= inv; a[j].w *= inv;
        po[j] = a[j];
    }
}

// ---------------------------------------------------------------------------
// Kernel 3c: O = P @ V per chunk. grid = B*NH*ACH, 256 threads.
//   Output rounded to tf32 so proj GEMM can cp.async it losslessly.
// ---------------------------------------------------------------------------
__global__ __launch_bounds__(256) void attn_pv_kernel()
{
    int blk = blockIdx.x;
    int bh = blk >> 3, ch = blk & 7;
    int b = bh >> 3, h = bh & 7;
    const float* v = g_qkv + ((size_t)b * 3 * CCH + 2 * CCH + (size_t)h * HD) * HW;
    float*       o = g_ao  + ((size_t)b * CCH + (size_t)h * HD) * HW;

    __shared__ float P[HD][HD + 1];
    int tid = threadIdx.x;
    for (int i = tid; i < HD * HD; i += 256)
        P[i >> 6][i & 63] = g_P[(size_t)bh * (HD * HD) + i];
    __syncthreads();

    const int nbeg = ch * CLEN;
    for (int n = nbeg + tid; n < nbeg + CLEN; n += 256) {
        float accv[HD];
        #pragma unroll
        for (int cc = 0; cc < HD; cc++) accv[cc] = 0.f;
        #pragma unroll 4
        for (int d = 0; d < HD; d++) {
            float vd = v[(size_t)d * HW + n];
            #pragma unroll
            for (int cc = 0; cc < HD; cc++)
                accv[cc] = fmaf(P[cc][d], vd, accv[cc]);
        }
        #pragma unroll
        for (int cc = 0; cc < HD; cc++)
            o[(size_t)cc * HW + n] = __uint_as_float(f2t(accv[cc]));
    }
}

// ---------------------------------------------------------------------------
// Launch
// ---------------------------------------------------------------------------
extern "C" void kernel_launch(void* const* d_in, const int* in_sizes, int n_in,
                              void* d_out, int out_size)
{
    const float* x      = (const float*)d_in[0];
    const float* gamma  = (const float*)d_in[1];
    const float* beta   = (const float*)d_in[2];
    const float* w_qkv  = (const float*)d_in[3];
    const float* b_qkv  = (const float*)d_in[4];
    const float* w_proj = (const float*)d_in[5];
    const float* b_proj = (const float*)d_in[6];
    float* out = (float*)d_out;

    float *qkv_ptr, *ao_ptr;
    uint32_t *wtq_ptr, *wtp_ptr;
    cudaGetSymbolAddress((void**)&qkv_ptr, g_qkv);
    cudaGetSymbolAddress((void**)&ao_ptr, g_ao);
    cudaGetSymbolAddress((void**)&wtq_ptr, g_wtq);
    cudaGetSymbolAddress((void**)&wtp_ptr, g_wtp);

    // 0) weight transpose + tf32 convert
    wt_kernel<<<512, 256>>>(w_qkv, w_proj);

    // 1) GroupNorm stats
    gn_stats_kernel<<<BATCH * NGRP, 256>>>(x, gamma, beta);

    // 2) qkv GEMM
    {
        dim3 grid(HW / 128, (3 * CCH) / 128, BATCH);
        gemm_mma<0><<<grid, 256>>>(x, wtq_ptr, b_qkv, nullptr, qkv_ptr, 3 * CCH);
    }

    // 3) attention (3 phases)
    attn_qk_kernel<<<BATCH * NH * ACH, 256>>>();
    attn_sm_kernel<<<BATCH * NH, 64>>>();
    attn_pv_kernel<<<BATCH * NH * ACH, 256>>>();

    // 4) proj GEMM
    {
        dim3 grid(HW / 128, CCH / 128, BATCH);
        gemm_mma<1><<<grid, 256>>>(ao_ptr, wtp_ptr, b_proj, x, out, CCH);
    }
}

// round 5
// speedup vs baseline: 3.2203x; 1.3343x over previous
#include <cuda_runtime.h>
#include <cstdint>

// Problem constants
#define BATCH 16
#define CCH   512
#define HW    4096
#define NGRP  32
#define CPG   16
#define NH    8
#define HD    64
#define EPSV  1e-5f
#define ACH   8
#define CLEN  (HW / ACH)   // 512

// ---------------------------------------------------------------------------
// Scratch (device globals)
// ---------------------------------------------------------------------------
__device__ float    g_qkv[(size_t)BATCH * 3 * CCH * HW];   // [b][o][n]
__device__ float    g_ao [(size_t)BATCH * CCH * HW];       // [b][c][n] tf32-valued
__device__ uint32_t g_xn [(size_t)BATCH * CCH * HW];       // GN(x) tf32 bits [b][c][n]
__device__ float    g_sc[BATCH * CCH];
__device__ float    g_bs[BATCH * CCH];
__device__ uint32_t g_wtq[24 * 64 * 32 * 20];              // W_qkv fragment blob
__device__ uint32_t g_wtp[ 8 * 64 * 32 * 20];              // W_proj fragment blob
__device__ float    g_sp[(size_t)BATCH * NH * ACH * HD * HD];
__device__ float    g_P [(size_t)BATCH * NH * HD * HD];

// ---------------------------------------------------------------------------
// helpers
// ---------------------------------------------------------------------------
__device__ __forceinline__ uint32_t f2t(float f) {
    uint32_t u;
    asm("cvt.rna.tf32.f32 %0, %1;" : "=r"(u) : "f"(f));
    return u;
}
__device__ __forceinline__ uint32_t sptr(const void* p) {
    uint32_t a;
    asm("{ .reg .u64 t; cvta.to.shared.u64 t, %1; cvt.u32.u64 %0, t; }" : "=r"(a) : "l"(p));
    return a;
}
__device__ __forceinline__ void cpa16(uint32_t dst, const void* src) {
    asm volatile("cp.async.cg.shared.global [%0], [%1], 16;" :: "r"(dst), "l"(src));
}
__device__ __forceinline__ void cpa_commit() { asm volatile("cp.async.commit_group;" ::: "memory"); }
__device__ __forceinline__ void cpa_wait2()  { asm volatile("cp.async.wait_group 2;" ::: "memory"); }

// ---------------------------------------------------------------------------
// Kernel 0: W -> fragment blob.  entry e = (m64*64 + k8)*32 + lane
//   word w (0..15): mf=w>>2, j=w&3
//   value = W[m64*64 + mf*16 + g4 + (j&1)*8][k8*8 + t4 + (j>>1)*4]
//   blob[e*20 + w]   (20-word padded lane stride: conflict-free lds.128)
// ---------------------------------------------------------------------------
__global__ __launch_bounds__(256) void wt_kernel(
    const float* __restrict__ Wq, const float* __restrict__ Wp)
{
    int idx = blockIdx.x * 256 + threadIdx.x;   // 65536 entries total
    const float* W; uint32_t* blob; int e;
    if (idx < 49152) { W = Wq; blob = g_wtq; e = idx; }
    else             { W = Wp; blob = g_wtp; e = idx - 49152; }
    int lane = e & 31, k8 = (e >> 5) & 63, m64 = e >> 11;
    int t4 = lane & 3, g4 = lane >> 2;
    uint32_t out[16];
    #pragma unroll
    for (int w = 0; w < 16; w++) {
        int mf = w >> 2, j = w & 3;
        int kk = k8 * 8 + t4 + ((j >> 1) << 2);
        int oo = m64 * 64 + mf * 16 + g4 + ((j & 1) << 3);
        out[w] = f2t(W[(size_t)oo * CCH + kk]);
    }
    uint32_t* dst = blob + (size_t)e * 20;
    #pragma unroll
    for (int q = 0; q < 4; q++)
        *(uint4*)(dst + q * 4) = make_uint4(out[q*4], out[q*4+1], out[q*4+2], out[q*4+3]);
}

// ---------------------------------------------------------------------------
// Kernel 1: GroupNorm stats -> fused per-channel scale/bias
// ---------------------------------------------------------------------------
__global__ __launch_bounds__(256) void gn_stats_kernel(
    const float* __restrict__ x,
    const float* __restrict__ gamma,
    const float* __restrict__ beta)
{
    int bg = blockIdx.x;
    int b = bg / NGRP, g = bg % NGRP;
    const float* xp = x + ((size_t)b * CCH + (size_t)g * CPG) * HW;

    int tid = threadIdx.x;
    float s = 0.f, ss = 0.f;
    const float4* xp4 = (const float4*)xp;
    const int n4 = (CPG * HW) / 4;
    for (int i = tid; i < n4; i += 256) {
        float4 v = xp4[i];
        s  += v.x + v.y + v.z + v.w;
        ss += v.x*v.x + v.y*v.y + v.z*v.z + v.w*v.w;
    }
    __shared__ float sh_s[256], sh_ss[256];
    sh_s[tid] = s; sh_ss[tid] = ss;
    __syncthreads();
    for (int off = 128; off > 0; off >>= 1) {
        if (tid < off) { sh_s[tid] += sh_s[tid+off]; sh_ss[tid] += sh_ss[tid+off]; }
        __syncthreads();
    }
    if (tid < CPG) {
        const float inv_n = 1.0f / (float)(CPG * HW);
        float mean = sh_s[0] * inv_n;
        float var  = sh_ss[0] * inv_n - mean * mean;
        float inv  = rsqrtf(var + EPSV);
        int c = g * CPG + tid;
        float ga = gamma[c], be = beta[c];
        g_sc[b * CCH + c] = ga * inv;
        g_bs[b * CCH + c] = be - mean * inv * ga;
    }
}

// ---------------------------------------------------------------------------
// Kernel 1b: normalize x -> tf32 bits (same FP chain as before: fmaf then cvt)
// ---------------------------------------------------------------------------
__global__ __launch_bounds__(256) void xn_kernel(const float* __restrict__ x)
{
    size_t i = (size_t)blockIdx.x * 256 + threadIdx.x;   // float4 index
    int row = (int)(i >> 10);          // HW/4 = 1024 float4 per row
    int b = row >> 9, c = row & 511;
    float sc = g_sc[b * CCH + c], bs = g_bs[b * CCH + c];
    float4 v = ((const float4*)x)[i];
    uint4 u = make_uint4(f2t(fmaf(v.x, sc, bs)), f2t(fmaf(v.y, sc, bs)),
                         f2t(fmaf(v.z, sc, bs)), f2t(fmaf(v.w, sc, bs)));
    ((uint4*)g_xn)[i] = u;
}

// ---------------------------------------------------------------------------
// Kernel 2: TF32 mma.sync GEMM, pure cp.async, 3-stage pipeline.
//   C[b][o][n] = sum_k W[o][k] * X[b][k][n]  (+bias[o]) (+res if RES)
// CTA 128x128, BK=16, 8 warps @ 64x32, A frags via lds.128 from W blob.
// ---------------------------------------------------------------------------
#define BK    16
#define WSTG  2560               // words per stage: W blob (2 m64 x 2 k8 x 640)
#define XSTG  (BK * 136)         // 2176 words
#define STGW  (WSTG + XSTG)      // 4736 words
#define GSMEM (3 * STGW * 4)     // 56832 bytes

template<int RES>
__global__ __launch_bounds__(256, 2) void gemm_mma(
    const uint32_t* __restrict__ Xsrc,   // [b][k][n] tf32 bits
    const uint32_t* __restrict__ Wblob,
    const float* __restrict__ bias,
    const float* __restrict__ res,
    float* __restrict__ Out,
    int MO)
{
    extern __shared__ uint32_t sm[];
    const int tid = threadIdx.x, lane = tid & 31, wid = tid >> 5;
    const int b = blockIdx.z, n0 = blockIdx.x * 128, o0 = blockIdx.y * 128;
    const int m64g = o0 >> 6;
    const uint32_t* Xp = Xsrc + (size_t)b * CCH * HW;
    const uint32_t smb = sptr(sm);

    const int wm = wid >> 2, wn = wid & 3;
    const int mb = wm * 64, nb = wn * 32;
    const int g4 = lane >> 2, t4 = lane & 3;

    auto issue = [&](int s) {
        const int slot = s % 3;
        const uint32_t wd = smb + (uint32_t)slot * STGW * 4;
        const uint32_t xd = wd + WSTG * 4;
        // W: 640 chunks; per m64 block 320 contiguous chunks (k8 pair 2s,2s+1)
        const uint32_t* src0 = Wblob + ((size_t)m64g * 64 + 2 * s) * 640;
        const uint32_t* src1 = Wblob + ((size_t)(m64g + 1) * 64 + 2 * s) * 640;
        {
            int c = tid;
            cpa16(wd + c * 16, src0 + c * 4);                       // 0..255 < 320
            c = tid + 256;
            cpa16(wd + c * 16, c < 320 ? src0 + c * 4 : src1 + (c - 320) * 4);
            if (tid < 128) { c = tid + 512; cpa16(wd + c * 16, src1 + (c - 320) * 4); }
        }
        // X: 512 chunks: row = c>>5, col = c&31
        {
            const int k0 = s * BK;
            int r = tid >> 5, col = tid & 31;
            cpa16(xd + (uint32_t)(r * 136 + col * 4) * 4,
                  Xp + (size_t)(k0 + r) * HW + n0 + col * 4);
            int c2 = tid + 256;
            r = c2 >> 5; col = c2 & 31;
            cpa16(xd + (uint32_t)(r * 136 + col * 4) * 4,
                  Xp + (size_t)(k0 + r) * HW + n0 + col * 4);
        }
        cpa_commit();
    };

    float acc[4][4][4];
    #pragma unroll
    for (int i = 0; i < 4; i++)
        #pragma unroll
        for (int j = 0; j < 4; j++)
            #pragma unroll
            for (int r = 0; r < 4; r++) acc[i][j][r] = 0.f;

    issue(0);
    issue(1);

    const int NS = CCH / BK;   // 32
    #pragma unroll 1
    for (int s = 0; s < NS; s++) {
        if (s > 0) __syncthreads();          // close compute(s-1) before slot reuse
        if (s + 2 < NS) issue(s + 2); else cpa_commit();   // keep group count uniform
        cpa_wait2();                          // stage s complete
        __syncthreads();

        const int slot = s % 3;
        const uint32_t* ws = sm + slot * STGW;
        const uint32_t* xs = ws + WSTG;

        #pragma unroll
        for (int ks = 0; ks < 2; ks++) {
            uint4 a4[4];
            const uint32_t* wbase = ws + wm * 1280 + ks * 640 + lane * 20;
            #pragma unroll
            for (int mf = 0; mf < 4; mf++)
                a4[mf] = *(const uint4*)(wbase + mf * 4);
            uint32_t bb[4][2];
            const uint32_t* x0 = xs + (ks * 8 + t4) * 136 + nb + g4;
            #pragma unroll
            for (int nf = 0; nf < 4; nf++) {
                bb[nf][0] = x0[nf * 8];
                bb[nf][1] = x0[4 * 136 + nf * 8];
            }
            #pragma unroll
            for (int mf = 0; mf < 4; mf++)
                #pragma unroll
                for (int nf = 0; nf < 4; nf++)
                    asm volatile(
                        "mma.sync.aligned.m16n8k8.row.col.f32.tf32.tf32.f32 "
                        "{%0,%1,%2,%3}, {%4,%5,%6,%7}, {%8,%9}, {%0,%1,%2,%3};"
                        : "+f"(acc[mf][nf][0]), "+f"(acc[mf][nf][1]),
                          "+f"(acc[mf][nf][2]), "+f"(acc[mf][nf][3])
                        : "r"(a4[mf].x), "r"(a4[mf].y), "r"(a4[mf].z), "r"(a4[mf].w),
                          "r"(bb[nf][0]), "r"(bb[nf][1]));
        }
    }

    // ---- epilogue ----
    #pragma unroll
    for (int mf = 0; mf < 4; mf++) {
        int row = o0 + mb + mf * 16 + g4;
        float bv0 = bias[row], bv1 = bias[row + 8];
        #pragma unroll
        for (int nf = 0; nf < 4; nf++) {
            int col = n0 + nb + nf * 8 + t4 * 2;
            size_t a0 = ((size_t)b * MO + row)     * HW + col;
            size_t a1 = ((size_t)b * MO + row + 8) * HW + col;
            float2 v0 = { acc[mf][nf][0] + bv0, acc[mf][nf][1] + bv0 };
            float2 v1 = { acc[mf][nf][2] + bv1, acc[mf][nf][3] + bv1 };
            if (RES) {
                float2 r0 = *(const float2*)(res + a0);
                float2 r1 = *(const float2*)(res + a1);
                v0.x += r0.x; v0.y += r0.y;
                v1.x += r1.x; v1.y += r1.y;
            }
            *(float2*)(Out + a0) = v0;
            *(float2*)(Out + a1) = v1;
        }
    }
}

// ---------------------------------------------------------------------------
// Kernel 3a: QK^T partials, vectorized. grid = B*NH*ACH, 256 threads.
//   Transposed swizzled tiles: qs[nn][col], col granule ^= (nn>>2)&7
// ---------------------------------------------------------------------------
__global__ __launch_bounds__(256) void attn_qk_kernel()
{
    int blk = blockIdx.x, bh = blk >> 3, ch = blk & 7;
    int b = bh >> 3, h = bh & 7;
    const float* q = g_qkv + ((size_t)b * 3 * CCH + (size_t)h * HD) * HW;
    const float* k = g_qkv + ((size_t)b * 3 * CCH + CCH + (size_t)h * HD) * HW;

    __shared__ float qs[32][64];
    __shared__ float ks[32][64];

    int tid = threadIdx.x;
    int ty = tid >> 4, tx = tid & 15;

    float acc[4][4] = {};
    const int nbeg = ch * CLEN;
    for (int n0 = nbeg; n0 < nbeg + CLEN; n0 += 32) {
        #pragma unroll
        for (int i = 0; i < 2; i++) {
            int idx = tid + i * 256;
            int c = idx >> 3, nn4 = idx & 7;
            float4 vq = *(const float4*)(q + (size_t)c * HW + n0 + nn4 * 4);
            float4 vk = *(const float4*)(k + (size_t)c * HW + n0 + nn4 * 4);
            int col = (((c >> 2) ^ nn4) << 2) | (c & 3);
            int r = nn4 * 4;
            qs[r+0][col] = vq.x; qs[r+1][col] = vq.y; qs[r+2][col] = vq.z; qs[r+3][col] = vq.w;
            ks[r+0][col] = vk.x; ks[r+1][col] = vk.y; ks[r+2][col] = vk.z; ks[r+3][col] = vk.w;
        }
        __syncthreads();
        #pragma unroll
        for (int kk = 0; kk < 32; kk++) {
            int sw = (kk >> 2) & 7;
            float4 rq = *(const float4*)&qs[kk][(ty ^ sw) << 2];
            float4 rk = *(const float4*)&ks[kk][(tx ^ sw) << 2];
            float rqa[4] = {rq.x, rq.y, rq.z, rq.w};
            float rka[4] = {rk.x, rk.y, rk.z, rk.w};
            #pragma unroll
            for (int i = 0; i < 4; i++)
                #pragma unroll
                for (int j = 0; j < 4; j++)
                    acc[i][j] = fmaf(rqa[i], rka[j], acc[i][j]);
        }
        __syncthreads();
    }

    float* sp = g_sp + (size_t)blk * (HD * HD);
    #pragma unroll
    for (int i = 0; i < 4; i++) {
        float4 v = { acc[i][0], acc[i][1], acc[i][2], acc[i][3] };
        *(float4*)(sp + (ty * 4 + i) * HD + tx * 4) = v;
    }
}

// ---------------------------------------------------------------------------
// Kernel 3b: reduce partials + softmax. grid = B*NH, 64 threads.
// ---------------------------------------------------------------------------
__global__ __launch_bounds__(64) void attn_sm_kernel()
{
    int bh = blockIdx.x;
    int r = threadIdx.x;

    float4 a[16];
    #pragma unroll
    for (int j = 0; j < 16; j++) a[j] = make_float4(0.f, 0.f, 0.f, 0.f);
    #pragma unroll
    for (int ch = 0; ch < ACH; ch++) {
        const float4* p = (const float4*)(g_sp + ((size_t)bh * ACH + ch) * (HD * HD) + r * HD);
        #pragma unroll
        for (int j = 0; j < 16; j++) {
            float4 v = p[j];
            a[j].x += v.x; a[j].y += v.y; a[j].z += v.z; a[j].w += v.w;
        }
    }
    const float scale = 0.125f;
    float mx = -1e30f;
    #pragma unroll
    for (int j = 0; j < 16; j++) {
        a[j].x *= scale; a[j].y *= scale; a[j].z *= scale; a[j].w *= scale;
        mx = fmaxf(mx, fmaxf(fmaxf(a[j].x, a[j].y), fmaxf(a[j].z, a[j].w)));
    }
    float sum = 0.f;
    #pragma unroll
    for (int j = 0; j < 16; j++) {
        a[j].x = __expf(a[j].x - mx); a[j].y = __expf(a[j].y - mx);
        a[j].z = __expf(a[j].z - mx); a[j].w = __expf(a[j].w - mx);
        sum += a[j].x + a[j].y + a[j].z + a[j].w;
    }
    float inv = 1.f / sum;
    float4* po = (float4*)(g_P + (size_t)bh * (HD * HD) + r * HD);
    #pragma unroll
    for (int j = 0; j < 16; j++) {
        a[j].x *= inv; a[j].y *= inv; a[j].z *= inv; a[j].w *= inv;
        po[j] = a[j];
    }
}

// ---------------------------------------------------------------------------
// Kernel 3c: O = P @ V, vectorized 64x64 tiles. grid = B*NH*ACH.
// ---------------------------------------------------------------------------
__global__ __launch_bounds__(256) void attn_pv_kernel()
{
    int blk = blockIdx.x, bh = blk >> 3, ch = blk & 7;
    int b = bh >> 3, h = bh & 7;
    const float* v = g_qkv + ((size_t)b * 3 * CCH + 2 * CCH + (size_t)h * HD) * HW;
    float*       o = g_ao  + ((size_t)b * CCH + (size_t)h * HD) * HW;

    __shared__ float Ps[HD][68];   // Ps[d][c] = P[c][d]
    __shared__ float vs[HD][64];   // granule-swizzled [d][n]

    int tid = threadIdx.x;
    int ty = tid >> 4, tx = tid & 15;

    const float* P = g_P + (size_t)bh * (HD * HD);
    #pragma unroll
    for (int i = 0; i < 4; i++) {
        int idx = tid + i * 256;
        int c = idx >> 4, d4 = idx & 15;
        float4 vP = *(const float4*)(P + c * HD + d4 * 4);
        Ps[d4*4+0][c] = vP.x; Ps[d4*4+1][c] = vP.y;
        Ps[d4*4+2][c] = vP.z; Ps[d4*4+3][c] = vP.w;
    }
    __syncthreads();

    const int nbeg = ch * CLEN;
    for (int n0 = nbeg; n0 < nbeg + CLEN; n0 += 64) {
        #pragma unroll
        for (int i = 0; i < 4; i++) {
            int idx = tid + i * 256;
            int d = idx >> 4, n4 = idx & 15;
            float4 vv = *(const float4*)(v + (size_t)d * HW + n0 + n4 * 4);
            int g = n4 ^ (d & 7);
            *(float4*)&vs[d][g * 4] = vv;
        }
        __syncthreads();

        float acc[4][4] = {};
        #pragma unroll 4
        for (int d = 0; d < HD; d++) {
            float4 rp = *(const float4*)&Ps[d][ty * 4];
            float4 rv = *(const float4*)&vs[d][(tx ^ (d & 7)) << 2];
            float rpa[4] = {rp.x, rp.y, rp.z, rp.w};
            float rva[4] = {rv.x, rv.y, rv.z, rv.w};
            #pragma unroll
            for (int i = 0; i < 4; i++)
                #pragma unroll
                for (int j = 0; j < 4; j++)
                    acc[i][j] = fmaf(rpa[i], rva[j], acc[i][j]);
        }

        #pragma unroll
        for (int ci = 0; ci < 4; ci++) {
            int c = ty * 4 + ci;
            float4 ov;
            ov.x = __uint_as_float(f2t(acc[ci][0]));
            ov.y = __uint_as_float(f2t(acc[ci][1]));
            ov.z = __uint_as_float(f2t(acc[ci][2]));
            ov.w = __uint_as_float(f2t(acc[ci][3]));
            *(float4*)(o + (size_t)c * HW + n0 + tx * 4) = ov;
        }
        __syncthreads();
    }
}

// ---------------------------------------------------------------------------
// Launch
// ---------------------------------------------------------------------------
extern "C" void kernel_launch(void* const* d_in, const int* in_sizes, int n_in,
                              void* d_out, int out_size)
{
    const float* x      = (const float*)d_in[0];
    const float* gamma  = (const float*)d_in[1];
    const float* beta   = (const float*)d_in[2];
    const float* w_qkv  = (const float*)d_in[3];
    const float* b_qkv  = (const float*)d_in[4];
    const float* w_proj = (const float*)d_in[5];
    const float* b_proj = (const float*)d_in[6];
    float* out = (float*)d_out;

    float *qkv_ptr, *ao_ptr;
    uint32_t *xn_ptr, *wtq_ptr, *wtp_ptr;
    cudaGetSymbolAddress((void**)&qkv_ptr, g_qkv);
    cudaGetSymbolAddress((void**)&ao_ptr,  g_ao);
    cudaGetSymbolAddress((void**)&xn_ptr,  g_xn);
    cudaGetSymbolAddress((void**)&wtq_ptr, g_wtq);
    cudaGetSymbolAddress((void**)&wtp_ptr, g_wtp);

    cudaFuncSetAttribute((const void*)gemm_mma<0>,
                         cudaFuncAttributeMaxDynamicSharedMemorySize, GSMEM);
    cudaFuncSetAttribute((const void*)gemm_mma<1>,
                         cudaFuncAttributeMaxDynamicSharedMemorySize, GSMEM);

    // 0) weight fragment blobs
    wt_kernel<<<256, 256>>>(w_qkv, w_proj);

    // 1) GroupNorm stats, then normalize to tf32 bits
    gn_stats_kernel<<<BATCH * NGRP, 256>>>(x, gamma, beta);
    xn_kernel<<<(int)(((size_t)BATCH * CCH * HW / 4) / 256), 256>>>(x);

    // 2) qkv GEMM
    {
        dim3 grid(HW / 128, (3 * CCH) / 128, BATCH);
        gemm_mma<0><<<grid, 256, GSMEM>>>(xn_ptr, wtq_ptr, b_qkv, nullptr, qkv_ptr, 3 * CCH);
    }

    // 3) attention
    attn_qk_kernel<<<BATCH * NH * ACH, 256>>>();
    attn_sm_kernel<<<BATCH * NH, 64>>>();
    attn_pv_kernel<<<BATCH * NH * ACH, 256>>>();

    // 4) proj GEMM (residual fused)
    {
        dim3 grid(HW / 128, CCH / 128, BATCH);
        gemm_mma<1><<<grid, 256, GSMEM>>>((const uint32_t*)ao_ptr, wtp_ptr, b_proj, x, out, CCH);
    }
}